// round 11
// baseline (speedup 1.0000x reference)
#include <cuda_runtime.h>
#include <cstdint>

// out[o,i,h,w] = sum_k weights[o,i,k] * x[k,h,w]
// OUT_CH = IN_CH = 2048, x is 3x3x3, output is (2048,2048,3,3) fp32.
//
// Streaming kernel, 128-thread blocks. Each thread computes 2 (o,i) pairs
// (18 floats), stages them in smem, and each warp drains its contiguous
// 2304B slice with a 1D TMA bulk store tagged L2::evict_first (output is
// write-once -> push writebacks early, keep the 50MB weight set L2-resident).
// x (27 floats) is read via __ldg (L1 broadcast hits) -> no block barrier.

__global__ void __launch_bounds__(128, 12) gf_layer_kernel(
    const float* __restrict__ x,
    const float* __restrict__ w,
    float* __restrict__ out) {
    __shared__ alignas(128) float sout[128 * 18];  // 9 KB staging tile

    const int tid = threadIdx.x;

    // First (o,i) pair handled by this thread (2 pairs per thread).
    const long long p = ((long long)blockIdx.x * 128 + tid) * 2;

    // 6 contiguous weights (2 pairs x 3 coeffs); byte offset p*12 is
    // 24B-aligned -> 3x float2 loads. w stays L2-resident (helped by
    // evict_first on the output stream).
    const float2* __restrict__ w2 = reinterpret_cast<const float2*>(w + p * 3);
    const float2 wa = w2[0];
    const float2 wb = w2[1];
    const float2 wc = w2[2];
    const float wv[6] = {wa.x, wa.y, wb.x, wb.y, wc.x, wc.y};

    // x: 27 floats, L1-cached broadcast reads.
    float xv[27];
#pragma unroll
    for (int j = 0; j < 27; j++) xv[j] = __ldg(&x[j]);

    float o[18];
#pragma unroll
    for (int pp = 0; pp < 2; pp++) {
        const float c0 = wv[pp * 3 + 0];
        const float c1 = wv[pp * 3 + 1];
        const float c2 = wv[pp * 3 + 2];
#pragma unroll
        for (int j = 0; j < 9; j++) {
            o[pp * 9 + j] =
                fmaf(c0, xv[j], fmaf(c1, xv[9 + j], c2 * xv[18 + j]));
        }
    }

    // Stage to smem as float2: thread stride = 18 floats = 72B. STS.64 phase
    // = 16 lanes; banks (18*l) mod 32 are 16 distinct even values ->
    // conflict-free.
    float2* __restrict__ s2 = reinterpret_cast<float2*>(sout + tid * 18);
#pragma unroll
    for (int i = 0; i < 9; i++) {
        s2[i] = make_float2(o[2 * i], o[2 * i + 1]);
    }

    // Per-warp TMA drain: warp wid owns sout[wid*576 .. +576) = 2304 bytes,
    // contiguous in both smem and gmem.
    const int wid = tid >> 5;
    const int lid = tid & 31;
    __syncwarp();

    if (lid == 0) {
        const float* ssrc = sout + wid * (32 * 18);
        uint32_t saddr;
        asm("{ .reg .u64 t; cvta.to.shared.u64 t, %1; cvt.u32.u64 %0, t; }"
            : "=r"(saddr) : "l"(ssrc));
        float* gdst =
            out + (long long)blockIdx.x * (128 * 18) + wid * (32 * 18);
        uint64_t pol;
        asm("createpolicy.fractional.L2::evict_first.b64 %0, 1.0;"
            : "=l"(pol));
        asm volatile("fence.proxy.async.shared::cta;" ::: "memory");
        asm volatile(
            "cp.async.bulk.global.shared::cta.bulk_group.L2::cache_hint "
            "[%0], [%1], %2, %3;"
            :: "l"(gdst), "r"(saddr), "r"(32 * 18 * 4), "l"(pol) : "memory");
        asm volatile("cp.async.bulk.commit_group;" ::: "memory");
        // Wait before this warp's smem slice may be torn down (block exit).
        asm volatile("cp.async.bulk.wait_group 0;" ::: "memory");
    }
}

extern "C" void kernel_launch(void* const* d_in, const int* in_sizes, int n_in,
                              void* d_out, int out_size) {
    // Inputs: x (27 elems), weights (2048*2048*3). Identify x by element count.
    const float* x;
    const float* w;
    long long w_elems;
    if (in_sizes[0] == 27) {
        x = (const float*)d_in[0];
        w = (const float*)d_in[1];
        w_elems = in_sizes[1];
    } else {
        x = (const float*)d_in[1];
        w = (const float*)d_in[0];
        w_elems = in_sizes[0];
    }

    float* out = (float*)d_out;

    const long long total_pairs = w_elems / 3;   // (o,i) pairs = 4,194,304
    const long long pairs_per_block = 128 * 2;   // 256
    const int blocks = (int)(total_pairs / pairs_per_block);  // 16384, exact

    gf_layer_kernel<<<blocks, 128>>>(x, w, out);
}